// round 7
// baseline (speedup 1.0000x reference)
#include <cuda_runtime.h>
#include <math.h>

#define BB 64
#define NN 17
#define CC 32
#define HW 4096   // 64*64

#define OFF_J 0           // joints: 64*17*2 = 2176
#define OFF_V 2176        // valid:  64*17   = 1088
#define OFF_K 3264        // new_keys: 64*17*32 = 34816
#define OFF_D 38080       // dist_x4: 64*17*256*256 = 71303168

__device__ float g_wdist[(size_t)BB * NN * HW];

// Analytic weight map (empirically identical to the literal 15-move loop)
__device__ __forceinline__ float weight_at(int x, int y, int kx, int ky) {
    int dx = abs(x - kx), dy = abs(y - ky);
    int m = 0;
    int mc = (dx > 0) ? dx : ((kx == 0 || kx == 63) ? 1 : 0);
    if (mc >= 1 && mc <= 15 && dy <= mc) m = mc;
    int mr = (dy > 0) ? dy : ((ky == 0 || ky == 63) ? 1 : 0);
    if (mr >= 1 && mr <= 15 && dx <= mr && mr > m) m = mr;
    return m ? (0.5f + 0.25f * (float)m) : 10.0f;
}

// ---------------- Kernel A: wdist (B,N,64,64) ----------------
__global__ void __launch_bounds__(512, 3) kA(const float* __restrict__ q,
                                             const float* __restrict__ keys,
                                             const int*   __restrict__ joints) {
    const int b = blockIdx.y;
    const int p = blockIdx.x * 512 + threadIdx.x;
    __shared__ __align__(16) float skey[NN][CC];
    __shared__ float sk2[NN];
    __shared__ int   skx[NN], sky[NN];
    const int t = threadIdx.x;
    if (t < NN * CC / 4)
        reinterpret_cast<float4*>(skey)[t] =
            reinterpret_cast<const float4*>(keys + b * NN * CC)[t];
    __syncthreads();
    if (t < NN) {
        float s = 0.f;   // mul+add sequential, no fma (XLA-faithful)
        for (int c = 0; c < CC; c++) s = __fadd_rn(s, __fmul_rn(skey[t][c], skey[t][c]));
        sk2[t] = s;
        skx[t] = joints[(b * NN + t) * 2 + 0];
        sky[t] = joints[(b * NN + t) * 2 + 1];
    }
    __syncthreads();

    float qv[CC];
    const float* qb = q + (size_t)b * CC * HW + p;
    float q2 = 0.f;
#pragma unroll
    for (int c = 0; c < CC; c++) {
        qv[c] = qb[(size_t)c * HW];
        q2 = __fadd_rn(q2, __fmul_rn(qv[c], qv[c]));
    }

    const int y = p >> 6, x = p & 63;
    float* wout = g_wdist + ((size_t)b * NN) * HW + p;
#pragma unroll 1
    for (int n = 0; n < NN; n++) {
        const float4* k4 = reinterpret_cast<const float4*>(skey[n]);
        float dot = 0.f;   // sequential ascending-c fmaf (gemm-faithful)
#pragma unroll
        for (int c4 = 0; c4 < CC / 4; c4++) {
            float4 kk = k4[c4];
            dot = fmaf(kk.x, qv[4 * c4 + 0], dot);
            dot = fmaf(kk.y, qv[4 * c4 + 1], dot);
            dot = fmaf(kk.z, qv[4 * c4 + 2], dot);
            dot = fmaf(kk.w, qv[4 * c4 + 3], dot);
        }
        float d2 = __fsub_rn(__fadd_rn(q2, sk2[n]), __fmul_rn(2.0f, dot));
        float dist = sqrtf(fmaxf(d2, 0.0f));
        float wm = weight_at(x, y, skx[n], sky[n]);
        wout[(size_t)n * HW] = __fmul_rn(dist, wm);
    }
}

// Bit-exact 4x4 upsample quad for input pixel (ti,tj). Deterministic:
// calling twice with identical sw yields identical bits.
__device__ __forceinline__ void upsample16(const float* __restrict__ sw,
                                           int ti, int tj, float4 (&o)[4]) {
    int yU = (ti > 0) ? ti - 1 : 0;
    int yD = (ti < 63) ? ti + 1 : 63;
    int xL = (tj > 0) ? tj - 1 : 0;
    int xR = (tj < 63) ? tj + 1 : 63;

    float up[3] = { sw[yU * 64 + xL], sw[yU * 64 + tj], sw[yU * 64 + xR] };
    float ce[3] = { sw[ti * 64 + xL], sw[ti * 64 + tj], sw[ti * 64 + xR] };
    float dn[3] = { sw[yD * 64 + xL], sw[yD * 64 + tj], sw[yD * 64 + xR] };

    float vy[4][3];
#pragma unroll
    for (int c3 = 0; c3 < 3; c3++) {
        if (ti == 0) { vy[0][c3] = ce[c3]; vy[1][c3] = ce[c3]; }
        else {
            vy[0][c3] = fmaf(0.625f, ce[c3], __fmul_rn(0.375f, up[c3]));
            vy[1][c3] = fmaf(0.875f, ce[c3], __fmul_rn(0.125f, up[c3]));
        }
        if (ti == 63) { vy[2][c3] = ce[c3]; vy[3][c3] = ce[c3]; }
        else {
            vy[2][c3] = fmaf(0.125f, dn[c3], __fmul_rn(0.875f, ce[c3]));
            vy[3][c3] = fmaf(0.375f, dn[c3], __fmul_rn(0.625f, ce[c3]));
        }
    }
#pragma unroll
    for (int r = 0; r < 4; r++) {
        float vL = vy[r][0], vC = vy[r][1], vR = vy[r][2];
        float o0, o1, o2, o3;
        if (tj == 0) { o0 = vC; o1 = vC; }
        else {
            o0 = fmaf(0.625f, vC, __fmul_rn(0.375f, vL));
            o1 = fmaf(0.875f, vC, __fmul_rn(0.125f, vL));
        }
        if (tj == 63) { o2 = vC; o3 = vC; }
        else {
            o2 = fmaf(0.125f, vR, __fmul_rn(0.875f, vC));
            o3 = fmaf(0.375f, vR, __fmul_rn(0.625f, vC));
        }
        o[r] = make_float4(o0, o1, o2, o3);
    }
}

// ---------------- Kernel B: upsample + argmins + outputs ----------------
// Hot loop tracks VALUES only (FMNMX); indices recovered by bit-exact
// recompute of the (few) tying threads + atomicMin (first-occurrence safe).
__global__ void __launch_bounds__(256, 8) kB(const float* __restrict__ q,
                                             const float* __restrict__ keys,
                                             float* __restrict__ out) {
    const int bn = blockIdx.x;
    const int b  = bn / NN;
    const int t  = threadIdx.x;

    __shared__ float sw[64 * 64];
    __shared__ float rv[256];
    __shared__ int   s_i0, s_si, s_valid;

    if (t == 0) { s_i0 = 0x7fffffff; s_si = 0x7fffffff; }

    // phase 1: load wdist into smem, value-only min
    const float* src = g_wdist + (size_t)bn * HW;
    float bv = 3.0e38f;
    for (int k = 0; k < 16; k++) {
        int idx = k * 256 + t;
        float v = src[idx];
        sw[idx] = v;
        bv = fminf(bv, v);
    }
    rv[t] = bv;
    __syncthreads();
    for (int s = 128; s > 0; s >>= 1) {
        if (t < s) rv[t] = fminf(rv[t], rv[t + s]);
        __syncthreads();
    }
    const float gmin1 = rv[0];
    __syncthreads();
    // argmin1 recovery: tying threads scan their own smem slice (ascending)
    if (bv == gmin1) {
        int first = 0x7fffffff;
        for (int k = 0; k < 16; k++) {
            int idx = k * 256 + t;
            if (sw[idx] == gmin1 && idx < first) first = idx;
        }
        atomicMin(&s_i0, first);
    }

    // phase 2: 4x bilinear upsample, value-only min
    float* od = out + OFF_D + (size_t)bn * 65536;
    float bv2 = 3.0e38f;
    for (int it = 0; it < 16; it++) {
        int T = it * 256 + t;
        int ti = T >> 6, tj = T & 63;
        float4 o[4];
        upsample16(sw, ti, tj, o);
#pragma unroll
        for (int r = 0; r < 4; r++) {
            int pbase = (4 * ti + r) * 256 + 4 * tj;
            *reinterpret_cast<float4*>(od + pbase) = o[r];
            bv2 = fminf(bv2, fminf(fminf(o[r].x, o[r].y), fminf(o[r].z, o[r].w)));
        }
    }

    __syncthreads();
    rv[t] = bv2;
    __syncthreads();
    for (int s = 128; s > 0; s >>= 1) {
        if (t < s) rv[t] = fminf(rv[t], rv[t + s]);
        __syncthreads();
    }
    const float gmin2 = rv[0];

    // argmin2 recovery: tying threads recompute (bit-exact) and report
    // their earliest flat index; atomicMin yields global first occurrence.
    if (bv2 == gmin2) {
        int first = 0x7fffffff;
        for (int it = 0; it < 16 && first == 0x7fffffff; it++) {
            int T = it * 256 + t;
            int ti = T >> 6, tj = T & 63;
            float4 o[4];
            upsample16(sw, ti, tj, o);
#pragma unroll
            for (int r = 0; r < 4; r++) {
                int pbase = (4 * ti + r) * 256 + 4 * tj;
                if (first == 0x7fffffff) {
                    if      (o[r].x == gmin2) first = pbase;
                    else if (o[r].y == gmin2) first = pbase + 1;
                    else if (o[r].z == gmin2) first = pbase + 2;
                    else if (o[r].w == gmin2) first = pbase + 3;
                }
            }
        }
        atomicMin(&s_si, first);
    }
    __syncthreads();

    if (t == 0) {
        int sidx = s_si;
        bool nonzero = false;
        for (int c = 0; c < CC; c++) nonzero |= (keys[bn * CC + c] != 0.0f);
        bool valid = nonzero && ((int)floorf(gmin1) <= 5);
        s_valid = valid ? 1 : 0;
        int sv = valid ? (sidx >> 8)  : -1;
        int sh = valid ? (sidx & 255) : -1;
        out[OFF_J + bn * 2 + 0] = (float)sv;
        out[OFF_J + bn * 2 + 1] = (float)sh;
        out[OFF_V + bn] = valid ? 1.0f : 0.0f;
    }
    __syncthreads();
    if (t < CC) {
        float nk = s_valid ? q[((size_t)b * CC + t) * HW + s_i0]
                           : keys[bn * CC + t];
        out[OFF_K + bn * CC + t] = nk;
    }
}

extern "C" void kernel_launch(void* const* d_in, const int* in_sizes, int n_in,
                              void* d_out, int out_size) {
    const float* q      = (const float*)d_in[0];
    const float* keys   = (const float*)d_in[1];
    const int*   joints = (const int*)  d_in[2];
    float* out = (float*)d_out;

    dim3 gA(8, BB);
    kA<<<gA, 512>>>(q, keys, joints);
    kB<<<BB * NN, 256>>>(q, keys, out);
}

// round 8
// speedup vs baseline: 1.1299x; 1.1299x over previous
#include <cuda_runtime.h>
#include <math.h>

#define BB 64
#define NN 17
#define CC 32
#define HW 4096   // 64*64

#define OFF_J 0           // joints: 64*17*2 = 2176
#define OFF_V 2176        // valid:  64*17   = 1088
#define OFF_K 3264        // new_keys: 64*17*32 = 34816
#define OFF_D 38080       // dist_x4: 64*17*256*256 = 71303168

__device__ float g_wdist[(size_t)BB * NN * HW];

// Analytic weight map (empirically identical to the literal 15-move loop)
__device__ __forceinline__ float weight_at(int x, int y, int kx, int ky) {
    int dx = abs(x - kx), dy = abs(y - ky);
    int m = 0;
    int mc = (dx > 0) ? dx : ((kx == 0 || kx == 63) ? 1 : 0);
    if (mc >= 1 && mc <= 15 && dy <= mc) m = mc;
    int mr = (dy > 0) ? dy : ((ky == 0 || ky == 63) ? 1 : 0);
    if (mr >= 1 && mr <= 15 && dx <= mr && mr > m) m = mr;
    return m ? (0.5f + 0.25f * (float)m) : 10.0f;
}

// ---------------- Kernel A: wdist (B,N,64,64) ---------------- (round-6 exact)
__global__ void __launch_bounds__(512) kA(const float* __restrict__ q,
                                          const float* __restrict__ keys,
                                          const int*   __restrict__ joints) {
    const int b = blockIdx.y;
    const int p = blockIdx.x * 512 + threadIdx.x;
    __shared__ __align__(16) float skey[NN][CC];
    __shared__ float sk2[NN];
    __shared__ int   skx[NN], sky[NN];
    const int t = threadIdx.x;
    if (t < NN * CC / 4)
        reinterpret_cast<float4*>(skey)[t] =
            reinterpret_cast<const float4*>(keys + b * NN * CC)[t];
    __syncthreads();
    if (t < NN) {
        float s = 0.f;   // mul+add sequential, no fma (XLA-faithful)
        for (int c = 0; c < CC; c++) s = __fadd_rn(s, __fmul_rn(skey[t][c], skey[t][c]));
        sk2[t] = s;
        skx[t] = joints[(b * NN + t) * 2 + 0];
        sky[t] = joints[(b * NN + t) * 2 + 1];
    }
    __syncthreads();

    float qv[CC];
    const float* qb = q + (size_t)b * CC * HW + p;
    float q2 = 0.f;
#pragma unroll
    for (int c = 0; c < CC; c++) {
        qv[c] = qb[(size_t)c * HW];
        q2 = __fadd_rn(q2, __fmul_rn(qv[c], qv[c]));
    }

    const int y = p >> 6, x = p & 63;
    float* wout = g_wdist + ((size_t)b * NN) * HW + p;
#pragma unroll 1
    for (int n = 0; n < NN; n++) {
        const float4* k4 = reinterpret_cast<const float4*>(skey[n]);
        float dot = 0.f;   // sequential ascending-c fmaf (gemm-faithful)
#pragma unroll
        for (int c4 = 0; c4 < CC / 4; c4++) {
            float4 kk = k4[c4];
            dot = fmaf(kk.x, qv[4 * c4 + 0], dot);
            dot = fmaf(kk.y, qv[4 * c4 + 1], dot);
            dot = fmaf(kk.z, qv[4 * c4 + 2], dot);
            dot = fmaf(kk.w, qv[4 * c4 + 3], dot);
        }
        float d2 = __fsub_rn(__fadd_rn(q2, sk2[n]), __fmul_rn(2.0f, dot));
        float dist = sqrtf(fmaxf(d2, 0.0f));
        float wm = weight_at(x, y, skx[n], sky[n]);
        wout[(size_t)n * HW] = __fmul_rn(dist, wm);
    }
}

// Bit-exact 4x4 upsample quad for input pixel (ti,tj); deterministic.
__device__ __forceinline__ void upsample16(const float* __restrict__ sw,
                                           int ti, int tj, float4 (&o)[4]) {
    int yU = (ti > 0) ? ti - 1 : 0;
    int yD = (ti < 63) ? ti + 1 : 63;
    int xL = (tj > 0) ? tj - 1 : 0;
    int xR = (tj < 63) ? tj + 1 : 63;

    float up[3] = { sw[yU * 64 + xL], sw[yU * 64 + tj], sw[yU * 64 + xR] };
    float ce[3] = { sw[ti * 64 + xL], sw[ti * 64 + tj], sw[ti * 64 + xR] };
    float dn[3] = { sw[yD * 64 + xL], sw[yD * 64 + tj], sw[yD * 64 + xR] };

    float vy[4][3];
#pragma unroll
    for (int c3 = 0; c3 < 3; c3++) {
        if (ti == 0) { vy[0][c3] = ce[c3]; vy[1][c3] = ce[c3]; }
        else {
            vy[0][c3] = fmaf(0.625f, ce[c3], __fmul_rn(0.375f, up[c3]));
            vy[1][c3] = fmaf(0.875f, ce[c3], __fmul_rn(0.125f, up[c3]));
        }
        if (ti == 63) { vy[2][c3] = ce[c3]; vy[3][c3] = ce[c3]; }
        else {
            vy[2][c3] = fmaf(0.125f, dn[c3], __fmul_rn(0.875f, ce[c3]));
            vy[3][c3] = fmaf(0.375f, dn[c3], __fmul_rn(0.625f, ce[c3]));
        }
    }
#pragma unroll
    for (int r = 0; r < 4; r++) {
        float vL = vy[r][0], vC = vy[r][1], vR = vy[r][2];
        float o0, o1, o2, o3;
        if (tj == 0) { o0 = vC; o1 = vC; }
        else {
            o0 = fmaf(0.625f, vC, __fmul_rn(0.375f, vL));
            o1 = fmaf(0.875f, vC, __fmul_rn(0.125f, vL));
        }
        if (tj == 63) { o2 = vC; o3 = vC; }
        else {
            o2 = fmaf(0.125f, vR, __fmul_rn(0.875f, vC));
            o3 = fmaf(0.375f, vR, __fmul_rn(0.625f, vC));
        }
        o[r] = make_float4(o0, o1, o2, o3);
    }
}

// ---------------- Kernel B: upsample + argmins + outputs ----------------
// Round-6 control flow; min tracking at QUAD granularity (fminf tree + one
// compare per 4 outputs). Element index resolved post-loop: phase 1 by one
// 16B smem re-read; phase 2 by one bit-exact quad recompute. Tie-break is
// exact: quads visited index-ascending (strict < keeps first quad), first
// matching element within the quad, (value,idx) lexicographic block reduce.
__global__ void __launch_bounds__(256, 8) kB(const float* __restrict__ q,
                                             const float* __restrict__ keys,
                                             float* __restrict__ out) {
    const int bn = blockIdx.x;
    const int b  = bn / NN;
    const int t  = threadIdx.x;

    __shared__ float sw[64 * 64];
    __shared__ float rv[256];
    __shared__ int   ri[256];
    __shared__ int   s_valid;

    // ---- phase 1: vectorized load + quad-min ----
    const float4* src4 = reinterpret_cast<const float4*>(g_wdist + (size_t)bn * HW);
    float4* sw4 = reinterpret_cast<float4*>(sw);
    float bv1 = 3.0e38f; int bq1 = 0;
#pragma unroll
    for (int k = 0; k < 4; k++) {
        int qid = k * 256 + t;                 // ascending per thread
        float4 v = src4[qid];
        sw4[qid] = v;
        float qm = fminf(fminf(v.x, v.y), fminf(v.z, v.w));
        if (qm < bv1) { bv1 = qm; bq1 = qid << 2; }
    }
    // resolve element within best quad (own write, no sync needed)
    {
        float4 v = sw4[bq1 >> 2];
        int ei;
        if      (v.x == bv1) ei = bq1;
        else if (v.y == bv1) ei = bq1 + 1;
        else if (v.z == bv1) ei = bq1 + 2;
        else                 ei = bq1 + 3;
        rv[t] = bv1; ri[t] = ei;
    }
    __syncthreads();
    for (int s = 128; s > 0; s >>= 1) {
        if (t < s) {
            float v2 = rv[t + s]; int i2 = ri[t + s];
            if (v2 < rv[t] || (v2 == rv[t] && i2 < ri[t])) { rv[t] = v2; ri[t] = i2; }
        }
        __syncthreads();
    }
    const float gmin1 = rv[0];
    const int   idx1  = ri[0];
    __syncthreads();   // rv/ri reused below

    // ---- phase 2: upsample + quad-min ----
    float* od = out + OFF_D + (size_t)bn * 65536;
    float bv2 = 3.0e38f; int bq2 = 0;
    for (int it = 0; it < 16; it++) {
        int T = it * 256 + t;
        int ti = T >> 6, tj = T & 63;
        float4 o[4];
        upsample16(sw, ti, tj, o);
        int pb = (4 * ti) * 256 + 4 * tj;
#pragma unroll
        for (int r = 0; r < 4; r++) {
            int pbase = pb + r * 256;
            *reinterpret_cast<float4*>(od + pbase) = o[r];
            float qm = fminf(fminf(o[r].x, o[r].y), fminf(o[r].z, o[r].w));
            if (qm < bv2) { bv2 = qm; bq2 = pbase; }   // ascending -> first quad
        }
    }
    // resolve element: bit-exact recompute of the best quad only
    {
        int row = bq2 >> 8;
        int ti = row >> 2, r = row & 3;
        int tj = (bq2 & 255) >> 2;
        float4 o[4];
        upsample16(sw, ti, tj, o);
        float4 v = o[r];
        int ei;
        if      (v.x == bv2) ei = bq2;
        else if (v.y == bv2) ei = bq2 + 1;
        else if (v.z == bv2) ei = bq2 + 2;
        else                 ei = bq2 + 3;
        rv[t] = bv2; ri[t] = ei;
    }
    __syncthreads();
    for (int s = 128; s > 0; s >>= 1) {
        if (t < s) {
            float v2 = rv[t + s]; int i2 = ri[t + s];
            if (v2 < rv[t] || (v2 == rv[t] && i2 < ri[t])) { rv[t] = v2; ri[t] = i2; }
        }
        __syncthreads();
    }

    if (t == 0) {
        int sidx = ri[0];
        bool nonzero = false;
        for (int c = 0; c < CC; c++) nonzero |= (keys[bn * CC + c] != 0.0f);
        bool valid = nonzero && ((int)floorf(gmin1) <= 5);
        s_valid = valid ? 1 : 0;
        int sv = valid ? (sidx >> 8)  : -1;
        int sh = valid ? (sidx & 255) : -1;
        out[OFF_J + bn * 2 + 0] = (float)sv;
        out[OFF_J + bn * 2 + 1] = (float)sh;
        out[OFF_V + bn] = valid ? 1.0f : 0.0f;
    }
    __syncthreads();
    if (t < CC) {
        float nk = s_valid ? q[((size_t)b * CC + t) * HW + idx1]
                           : keys[bn * CC + t];
        out[OFF_K + bn * CC + t] = nk;
    }
}

extern "C" void kernel_launch(void* const* d_in, const int* in_sizes, int n_in,
                              void* d_out, int out_size) {
    const float* q      = (const float*)d_in[0];
    const float* keys   = (const float*)d_in[1];
    const int*   joints = (const int*)  d_in[2];
    float* out = (float*)d_out;

    dim3 gA(8, BB);
    kA<<<gA, 512>>>(q, keys, joints);
    kB<<<BB * NN, 256>>>(q, keys, out);
}